// round 15
// baseline (speedup 1.0000x reference)
#include <cuda_runtime.h>
#include <cuda_bf16.h>
#include <cstdint>
#include <cstddef>

// ============================================================================
// WeightOnlyInt8Linear: out[m,n] = (x[m,:] . w[n,:]) * scale[n]
//   M = 8192, N = 4096, K = 4096;  x fp32, w int8-valued but delivered as
//   INT32 (harness dtype set is {float32, int32, bfloat16}), scale fp32.
//
// R13/R14 forensics: two independent GEMM load paths gave bit-identical
// rel_err = 1.117956 = sqrt(1.25) -> uncorrelated output with 0.25x variance
// -> weights were being read as int8 bytes of an int32 tensor. GEMM itself
// is consistent/correct. Fix: convert kernel reads int32.
//
// GEMM: mma.sync.m16n8k16.bf16 + ldmatrix + SW128 + 6-stage cp.async
// (sm_103 baseline ISA; tcgen05 unavailable at this build target).
//
// Accuracy: split-bf16. x = hi + lo (lo = bf16(x - hi)), interleaved along K
// into A'[M, 2K]; weights duplicated into B'[N, 2K] (int8 exact in bf16).
// One bf16 GEMM over K' = 8192 gives rel err ~1e-5 (gate: 1e-3).
// ============================================================================

static constexpr int MT = 8192;
static constexpr int NT = 4096;
static constexpr int KT = 4096;
static constexpr int K2 = 2 * KT;          // 8192

static constexpr int BM = 128;
static constexpr int BN = 128;
static constexpr int NITER = K2 / 64;      // 128 k-stages of 64 bf16 (128B)
static constexpr int NS = 6;               // pipeline stages

static constexpr int STAGE_BYTES = 2 * BM * 128;      // A 16KB + B 16KB
static constexpr int SC_OFF      = NS * STAGE_BYTES;  // 196608
static constexpr int SMEM_TOTAL  = SC_OFF + 512;      // 197120

static constexpr int GRID_M = MT / BM;     // 64
static constexpr int GRID_N = NT / BN;     // 32
static constexpr int GROUP_M = 8;          // CTA swizzle group width

// Scratch: __device__ globals are the sanctioned alloc-free path.
__device__ __align__(1024) __nv_bfloat16 g_A[(size_t)MT * K2];  // 128 MB
__device__ __align__(1024) __nv_bfloat16 g_B[(size_t)NT * K2];  //  64 MB

#define SW128(o) ((o) ^ (((o) >> 3) & 0x70))

__device__ __forceinline__ uint32_t smem_u32(const void* p) {
    uint32_t a;
    asm("{ .reg .u64 t; cvta.to.shared.u64 t, %1; cvt.u32.u64 %0, t; }"
        : "=r"(a) : "l"(p));
    return a;
}

__device__ __forceinline__ void cp_async16(uint32_t smem_addr, const void* gmem) {
    asm volatile("cp.async.cg.shared.global [%0], [%1], 16;"
                 :: "r"(smem_addr), "l"(gmem) : "memory");
}
#define CP_COMMIT() asm volatile("cp.async.commit_group;" ::: "memory")
#define CP_WAIT4()  asm volatile("cp.async.wait_group 4;" ::: "memory")
#define CP_WAIT0()  asm volatile("cp.async.wait_group 0;" ::: "memory")

__device__ __forceinline__ void ldsm4(uint32_t* r, uint32_t addr) {
    asm volatile("ldmatrix.sync.aligned.m8n8.x4.shared.b16 {%0,%1,%2,%3}, [%4];"
                 : "=r"(r[0]), "=r"(r[1]), "=r"(r[2]), "=r"(r[3]) : "r"(addr));
}

__device__ __forceinline__ void mma16816(float* d, const uint32_t* a,
                                         uint32_t b0, uint32_t b1) {
    asm volatile(
        "mma.sync.aligned.m16n8k16.row.col.f32.bf16.bf16.f32 "
        "{%0,%1,%2,%3}, {%4,%5,%6,%7}, {%8,%9}, {%0,%1,%2,%3};\n"
        : "+f"(d[0]), "+f"(d[1]), "+f"(d[2]), "+f"(d[3])
        : "r"(a[0]), "r"(a[1]), "r"(a[2]), "r"(a[3]), "r"(b0), "r"(b1));
}

// ---------------------------------------------------------------------------
// Phase 1a: fp32 x -> interleaved (hi, lo) bf16 rows of A'
// ---------------------------------------------------------------------------
__global__ void cvt_a_kernel(const float* __restrict__ x) {
    size_t i = (size_t)blockIdx.x * blockDim.x + threadIdx.x;  // one float4
    float4 v = reinterpret_cast<const float4*>(x)[i];
    float vals[4] = {v.x, v.y, v.z, v.w};
    uint4 u;
    __nv_bfloat16* o = reinterpret_cast<__nv_bfloat16*>(&u);
#pragma unroll
    for (int t = 0; t < 4; t++) {
        __nv_bfloat16 hi = __float2bfloat16(vals[t]);
        float r = vals[t] - __bfloat162float(hi);
        o[2 * t]     = hi;
        o[2 * t + 1] = __float2bfloat16(r);
    }
    reinterpret_cast<uint4*>(g_A)[i] = u;
}

// ---------------------------------------------------------------------------
// Phase 1b: INT32 weights (int8-valued) -> duplicated bf16 rows of B'
// ---------------------------------------------------------------------------
__global__ void cvt_b_kernel(const int* __restrict__ w) {
    size_t i = (size_t)blockIdx.x * blockDim.x + threadIdx.x;  // one int4
    int4 c = reinterpret_cast<const int4*>(w)[i];
    uint4 u;
    __nv_bfloat16* o = reinterpret_cast<__nv_bfloat16*>(&u);
    o[0] = o[1] = __float2bfloat16((float)c.x);
    o[2] = o[3] = __float2bfloat16((float)c.y);
    o[4] = o[5] = __float2bfloat16((float)c.z);
    o[6] = o[7] = __float2bfloat16((float)c.w);
    reinterpret_cast<uint4*>(g_B)[i] = u;
}

// ---------------------------------------------------------------------------
// Phase 2: bf16 mma.sync GEMM, 128x128 CTA tile, 6-stage cp.async pipeline.
// 256 threads = 8 warps in a 2(m) x 4(n) grid; warp tile 64x32.
// (Bit-identical results to the R14 verified-layout path; proven by bench.)
// ---------------------------------------------------------------------------
__global__ void __launch_bounds__(256, 1)
gemm_kernel(const float* __restrict__ scaler, float* __restrict__ out) {
    extern __shared__ char smem[];
    const uint32_t sb = smem_u32(smem);
    const int tid  = threadIdx.x;
    const int lane = tid & 31;
    const int wid  = tid >> 5;
    const int wm   = wid >> 2;   // 0..1 -> m offset 64*wm
    const int wn   = wid & 3;    // 0..3 -> n offset 32*wn

    // CTA swizzle: waves cover GROUP_M m-tiles x ~(148/GROUP_M) n-tiles.
    const int pid        = blockIdx.x;
    const int group_size = GROUP_M * GRID_N;
    const int group_id   = pid / group_size;
    const int pid_in     = pid - group_id * group_size;
    const int m_tile     = group_id * GROUP_M + (pid_in % GROUP_M);
    const int n_tile     = pid_in / GROUP_M;
    const int m0 = m_tile * BM;
    const int n0 = n_tile * BN;

    if (tid < BN)
        reinterpret_cast<float*>(smem + SC_OFF)[tid] = scaler[n0 + tid];

    // --- cp.async assignment: 4 x 16B chunks per tile per thread -----------
    const int lrow = tid >> 3;   // 0..31
    const int lcol = tid & 7;    // 16B column
    uint32_t sA[4], sBs[4];
    const char* gA[4];
    const char* gB[4];
#pragma unroll
    for (int j = 0; j < 4; j++) {
        int row = lrow + 32 * j;
        uint32_t off = SW128((uint32_t)(row * 128 + lcol * 16));
        sA[j]  = sb + off;
        sBs[j] = sb + 16384u + off;
        gA[j] = reinterpret_cast<const char*>(g_A + (size_t)(m0 + row) * K2) + lcol * 16;
        gB[j] = reinterpret_cast<const char*>(g_B + (size_t)(n0 + row) * K2) + lcol * 16;
    }

    // --- ldmatrix address precompute ---------------------------------------
    // offset(row, kb) = row*128 + kb; swizzle XOR mask = (row & 7) << 4, and
    // row & 7 == lane & 7 for all our fragments.
    const uint32_t swmask = (uint32_t)(lane & 7) << 4;
    const uint32_t lc16   = (uint32_t)(lane >> 4) << 4;  // k-halves split
    uint32_t preA[4], preB[2];
#pragma unroll
    for (int mi = 0; mi < 4; mi++)
        preA[mi] = (uint32_t)((wm * 64 + mi * 16 + (lane & 15)) * 128) + lc16;
#pragma unroll
    for (int bi = 0; bi < 2; bi++)
        preB[bi] = 16384u + (uint32_t)((wn * 32 + bi * 16 + (lane & 15)) * 128) + lc16;

    float acc[4][4][4];
#pragma unroll
    for (int mi = 0; mi < 4; mi++)
#pragma unroll
        for (int nj = 0; nj < 4; nj++)
#pragma unroll
            for (int c = 0; c < 4; c++) acc[mi][nj][c] = 0.0f;

    // --- prologue: stages 0..NS-2 ------------------------------------------
#pragma unroll
    for (int p = 0; p < NS - 1; p++) {
        uint32_t st = (uint32_t)(p * STAGE_BYTES);
        int go = p * 128;
#pragma unroll
        for (int j = 0; j < 4; j++) {
            cp_async16(sA[j] + st, gA[j] + go);
            cp_async16(sBs[j] + st, gB[j] + go);
        }
        CP_COMMIT();
    }

    // --- mainloop -----------------------------------------------------------
    for (int it = 0; it < NITER; it++) {
        CP_WAIT4();            // stage `it` resident
        __syncthreads();       // all warps done with stage (it-1)%NS

        const int jt = it + NS - 1;
        if (jt < NITER) {      // refill slot (it-1)%NS
            uint32_t st = (uint32_t)((jt % NS) * STAGE_BYTES);
            int go = jt * 128;
#pragma unroll
            for (int j = 0; j < 4; j++) {
                cp_async16(sA[j] + st, gA[j] + go);
                cp_async16(sBs[j] + st, gB[j] + go);
            }
        }
        CP_COMMIT();           // empty group in tail keeps wait_group math fixed

        const uint32_t stage = sb + (uint32_t)((it % NS) * STAGE_BYTES);
#pragma unroll
        for (int ks = 0; ks < 4; ks++) {
            uint32_t af[4][4], bfr[2][4];
#pragma unroll
            for (int mi = 0; mi < 4; mi++)
                ldsm4(af[mi], stage + ((preA[mi] + ks * 32) ^ swmask));
#pragma unroll
            for (int bi = 0; bi < 2; bi++)
                ldsm4(bfr[bi], stage + ((preB[bi] + ks * 32) ^ swmask));
#pragma unroll
            for (int mi = 0; mi < 4; mi++) {
#pragma unroll
                for (int nj = 0; nj < 4; nj++) {
                    uint32_t b0 = bfr[nj >> 1][nj & 1];
                    uint32_t b1 = bfr[nj >> 1][(nj & 1) + 2];
                    mma16816(acc[mi][nj], af[mi], b0, b1);
                }
            }
        }
    }
    CP_WAIT0();  // drain before exit

    // --- epilogue: scale and store (d0,d1 row r; d2,d3 row r+8) -------------
    const float* sc = reinterpret_cast<const float*>(smem + SC_OFF);
#pragma unroll
    for (int mi = 0; mi < 4; mi++) {
        int r = m0 + wm * 64 + mi * 16 + (lane >> 2);
        float* o0 = out + (size_t)r * NT + n0;
        float* o1 = out + (size_t)(r + 8) * NT + n0;
#pragma unroll
        for (int nj = 0; nj < 4; nj++) {
            int nl = wn * 32 + nj * 8 + (lane & 3) * 2;
            float s0 = sc[nl], s1 = sc[nl + 1];
            float2 v0 = make_float2(acc[mi][nj][0] * s0, acc[mi][nj][1] * s1);
            float2 v1 = make_float2(acc[mi][nj][2] * s0, acc[mi][nj][3] * s1);
            *reinterpret_cast<float2*>(o0 + nl) = v0;
            *reinterpret_cast<float2*>(o1 + nl) = v1;
        }
    }
}

// ---------------------------------------------------------------------------
// Launch
// ---------------------------------------------------------------------------
extern "C" void kernel_launch(void* const* d_in, const int* in_sizes, int n_in,
                              void* d_out, int out_size) {
    const float* x   = (const float*)d_in[0];  // [8192, 4096] fp32
    const int*   wq  = (const int*)d_in[1];    // [4096, 4096] int32 (int8 values)
    const float* sc  = (const float*)d_in[2];  // [4096] fp32
    float*       out = (float*)d_out;          // [8192, 4096] fp32

    cvt_a_kernel<<<(int)(((size_t)MT * KT / 4) / 256), 256>>>(x);
    cvt_b_kernel<<<(int)(((size_t)NT * KT / 4) / 256), 256>>>(wq);

    cudaFuncSetAttribute(gemm_kernel,
                         cudaFuncAttributeMaxDynamicSharedMemorySize, SMEM_TOTAL);
    gemm_kernel<<<GRID_M * GRID_N, 256, SMEM_TOTAL>>>(sc, out);
}

// round 16
// speedup vs baseline: 2.1313x; 2.1313x over previous
#include <cuda_runtime.h>
#include <cuda_fp16.h>
#include <cstdint>
#include <cstddef>

// ============================================================================
// WeightOnlyInt8Linear: out[m,n] = (x[m,:] . w[n,:]) * scale[n]
//   M = 8192, N = 4096, K = 4096; x fp32, w int8-valued delivered as INT32,
//   scale fp32, out fp32.
//
// R15 passed (1663 us) with split-bf16 (rel_err 9.9e-6, model-calibrated).
// GEMM was issue-bound (eff rt ~13.4 cyc/HMMA). This round:
//   1) fp16 instead of split-bf16: weights exact in fp16, x quantization
//      rel_err ~2.8e-4 < 1e-3 gate. Halves all tensor work (K'=4096).
//   2) warp tile 64x64 (CTA 128x256): mma:ldsm ratio 2.67 -> 4, half the
//      sync intervals.
// mma.sync.m16n8k16.f16 + ldmatrix + SW128 + 4-stage cp.async (sm_103 ISA).
// ============================================================================

static constexpr int MT = 8192;
static constexpr int NT = 4096;
static constexpr int KT = 4096;                // fp16 K
static constexpr int ROWB = KT * 2;            // 8192 B per row in g_A/g_B

static constexpr int BM = 128;
static constexpr int BN = 256;
static constexpr int NITER = KT / 64;          // 64 k-stages of 64 fp16 (128B)
static constexpr int NS = 4;                   // pipeline stages

static constexpr int B_OFF       = BM * 128;              // 16384 (A tile size)
static constexpr int STAGE_BYTES = (BM + BN) * 128;       // 49152
static constexpr int SC_OFF      = NS * STAGE_BYTES;      // 196608
static constexpr int SMEM_TOTAL  = SC_OFF + BN * 4;       // 197632

static constexpr int GRID_M = MT / BM;         // 64
static constexpr int GRID_N = NT / BN;         // 16
static constexpr int GROUP_M = 8;              // CTA swizzle group width

// Scratch: __device__ globals are the sanctioned alloc-free path.
__device__ __align__(1024) __half g_A[(size_t)MT * KT];   // 64 MB
__device__ __align__(1024) __half g_B[(size_t)NT * KT];   // 32 MB

#define SW128(o) ((o) ^ (((o) >> 3) & 0x70))

__device__ __forceinline__ uint32_t smem_u32(const void* p) {
    uint32_t a;
    asm("{ .reg .u64 t; cvta.to.shared.u64 t, %1; cvt.u32.u64 %0, t; }"
        : "=r"(a) : "l"(p));
    return a;
}

__device__ __forceinline__ void cp_async16(uint32_t smem_addr, const void* gmem) {
    asm volatile("cp.async.cg.shared.global [%0], [%1], 16;"
                 :: "r"(smem_addr), "l"(gmem) : "memory");
}
#define CP_COMMIT() asm volatile("cp.async.commit_group;" ::: "memory")
#define CP_WAIT2()  asm volatile("cp.async.wait_group 2;" ::: "memory")
#define CP_WAIT0()  asm volatile("cp.async.wait_group 0;" ::: "memory")

__device__ __forceinline__ void ldsm4(uint32_t* r, uint32_t addr) {
    asm volatile("ldmatrix.sync.aligned.m8n8.x4.shared.b16 {%0,%1,%2,%3}, [%4];"
                 : "=r"(r[0]), "=r"(r[1]), "=r"(r[2]), "=r"(r[3]) : "r"(addr));
}

__device__ __forceinline__ void mma16816(float* d, const uint32_t* a,
                                         uint32_t b0, uint32_t b1) {
    asm volatile(
        "mma.sync.aligned.m16n8k16.row.col.f32.f16.f16.f32 "
        "{%0,%1,%2,%3}, {%4,%5,%6,%7}, {%8,%9}, {%0,%1,%2,%3};\n"
        : "+f"(d[0]), "+f"(d[1]), "+f"(d[2]), "+f"(d[3])
        : "r"(a[0]), "r"(a[1]), "r"(a[2]), "r"(a[3]), "r"(b0), "r"(b1));
}

// ---------------------------------------------------------------------------
// Phase 1a: fp32 x -> fp16 rows of A' (8 elems / thread)
// ---------------------------------------------------------------------------
__global__ void cvt_a_kernel(const float* __restrict__ x) {
    size_t i = (size_t)blockIdx.x * blockDim.x + threadIdx.x;
    const float4* x4 = reinterpret_cast<const float4*>(x) + i * 2;
    float4 v0 = x4[0];
    float4 v1 = x4[1];
    uint4 u;
    __half* o = reinterpret_cast<__half*>(&u);
    o[0] = __float2half_rn(v0.x); o[1] = __float2half_rn(v0.y);
    o[2] = __float2half_rn(v0.z); o[3] = __float2half_rn(v0.w);
    o[4] = __float2half_rn(v1.x); o[5] = __float2half_rn(v1.y);
    o[6] = __float2half_rn(v1.z); o[7] = __float2half_rn(v1.w);
    reinterpret_cast<uint4*>(g_A)[i] = u;
}

// ---------------------------------------------------------------------------
// Phase 1b: INT32 weights (int8 values, exact in fp16) -> fp16 rows of B'
// ---------------------------------------------------------------------------
__global__ void cvt_b_kernel(const int* __restrict__ w) {
    size_t i = (size_t)blockIdx.x * blockDim.x + threadIdx.x;
    const int4* w4 = reinterpret_cast<const int4*>(w) + i * 2;
    int4 c0 = w4[0];
    int4 c1 = w4[1];
    uint4 u;
    __half* o = reinterpret_cast<__half*>(&u);
    o[0] = __float2half_rn((float)c0.x); o[1] = __float2half_rn((float)c0.y);
    o[2] = __float2half_rn((float)c0.z); o[3] = __float2half_rn((float)c0.w);
    o[4] = __float2half_rn((float)c1.x); o[5] = __float2half_rn((float)c1.y);
    o[6] = __float2half_rn((float)c1.z); o[7] = __float2half_rn((float)c1.w);
    reinterpret_cast<uint4*>(g_B)[i] = u;
}

// ---------------------------------------------------------------------------
// Phase 2: fp16 mma.sync GEMM, 128x256 CTA tile, 4-stage cp.async pipeline.
// 256 threads = 8 warps in a 2(m) x 4(n) grid; warp tile 64x64.
// ---------------------------------------------------------------------------
__global__ void __launch_bounds__(256, 1)
gemm_kernel(const float* __restrict__ scaler, float* __restrict__ out) {
    extern __shared__ char smem[];
    const uint32_t sb = smem_u32(smem);
    const int tid  = threadIdx.x;
    const int lane = tid & 31;
    const int wid  = tid >> 5;
    const int wm   = wid >> 2;   // 0..1 -> m offset 64*wm
    const int wn   = wid & 3;    // 0..3 -> n offset 64*wn

    // CTA swizzle: waves cover GROUP_M m-tiles x GRID_N n-tiles.
    const int pid        = blockIdx.x;
    const int group_size = GROUP_M * GRID_N;     // 128
    const int group_id   = pid / group_size;
    const int pid_in     = pid - group_id * group_size;
    const int m_tile     = group_id * GROUP_M + (pid_in % GROUP_M);
    const int n_tile     = pid_in / GROUP_M;
    const int m0 = m_tile * BM;
    const int n0 = n_tile * BN;

    reinterpret_cast<float*>(smem + SC_OFF)[tid] = scaler[n0 + tid];

    // --- cp.async assignment: A 4 chunks, B 8 chunks (16B each) per thread --
    const int lrow = tid >> 3;   // 0..31
    const int lcol = tid & 7;    // 16B column
    uint32_t sA[4], sBs[8];
#pragma unroll
    for (int j = 0; j < 4; j++)
        sA[j]  = sb + SW128((uint32_t)((lrow + 32 * j) * 128 + lcol * 16));
#pragma unroll
    for (int j = 0; j < 8; j++)
        sBs[j] = sb + (uint32_t)B_OFF
               + SW128((uint32_t)((lrow + 32 * j) * 128 + lcol * 16));
    const char* gAb = reinterpret_cast<const char*>(g_A)
                    + (size_t)(m0 + lrow) * ROWB + lcol * 16;
    const char* gBb = reinterpret_cast<const char*>(g_B)
                    + (size_t)(n0 + lrow) * ROWB + lcol * 16;

    // --- ldmatrix address precompute (row & 7 == lane & 7 for all frags) ----
    const uint32_t swmask = (uint32_t)(lane & 7) << 4;
    const uint32_t lc16   = (uint32_t)(lane >> 4) << 4;  // k-halves split
    uint32_t preA[4], preB[4];
#pragma unroll
    for (int mi = 0; mi < 4; mi++)
        preA[mi] = (uint32_t)((wm * 64 + mi * 16 + (lane & 15)) * 128) + lc16;
#pragma unroll
    for (int bi = 0; bi < 4; bi++)
        preB[bi] = (uint32_t)B_OFF
                 + (uint32_t)((wn * 64 + bi * 16 + (lane & 15)) * 128) + lc16;

    float acc[4][8][4];
#pragma unroll
    for (int mi = 0; mi < 4; mi++)
#pragma unroll
        for (int nj = 0; nj < 8; nj++)
#pragma unroll
            for (int c = 0; c < 4; c++) acc[mi][nj][c] = 0.0f;

    // --- prologue: stages 0..NS-2 ------------------------------------------
#pragma unroll
    for (int p = 0; p < NS - 1; p++) {
        uint32_t st = (uint32_t)(p * STAGE_BYTES);
        int go = p * 128;
#pragma unroll
        for (int j = 0; j < 4; j++)
            cp_async16(sA[j] + st, gAb + (size_t)j * 32 * ROWB + go);
#pragma unroll
        for (int j = 0; j < 8; j++)
            cp_async16(sBs[j] + st, gBb + (size_t)j * 32 * ROWB + go);
        CP_COMMIT();
    }

    // --- mainloop -----------------------------------------------------------
    for (int it = 0; it < NITER; it++) {
        CP_WAIT2();            // stage `it` resident (<= NS-2 groups pending)
        __syncthreads();       // all warps done with stage (it-1)%NS

        const int jt = it + NS - 1;
        if (jt < NITER) {      // refill slot (it-1)%NS
            uint32_t st = (uint32_t)((jt % NS) * STAGE_BYTES);
            int go = jt * 128;
#pragma unroll
            for (int j = 0; j < 4; j++)
                cp_async16(sA[j] + st, gAb + (size_t)j * 32 * ROWB + go);
#pragma unroll
            for (int j = 0; j < 8; j++)
                cp_async16(sBs[j] + st, gBb + (size_t)j * 32 * ROWB + go);
        }
        CP_COMMIT();           // empty group in tail keeps wait_group math fixed

        const uint32_t stage = sb + (uint32_t)((it % NS) * STAGE_BYTES);
#pragma unroll
        for (int ks = 0; ks < 4; ks++) {
            uint32_t af[4][4], bfr[4][4];
#pragma unroll
            for (int mi = 0; mi < 4; mi++)
                ldsm4(af[mi], stage + ((preA[mi] + ks * 32) ^ swmask));
#pragma unroll
            for (int bi = 0; bi < 4; bi++)
                ldsm4(bfr[bi], stage + ((preB[bi] + ks * 32) ^ swmask));
#pragma unroll
            for (int mi = 0; mi < 4; mi++) {
#pragma unroll
                for (int nj = 0; nj < 8; nj++) {
                    uint32_t b0 = bfr[nj >> 1][nj & 1];
                    uint32_t b1 = bfr[nj >> 1][(nj & 1) + 2];
                    mma16816(acc[mi][nj], af[mi], b0, b1);
                }
            }
        }
    }
    CP_WAIT0();  // drain before exit

    // --- epilogue: scale and store (d0,d1 row r; d2,d3 row r+8) -------------
    const float* sc = reinterpret_cast<const float*>(smem + SC_OFF);
#pragma unroll
    for (int mi = 0; mi < 4; mi++) {
        int r = m0 + wm * 64 + mi * 16 + (lane >> 2);
        float* o0 = out + (size_t)r * NT + n0;
        float* o1 = out + (size_t)(r + 8) * NT + n0;
#pragma unroll
        for (int nj = 0; nj < 8; nj++) {
            int nl = wn * 64 + nj * 8 + (lane & 3) * 2;
            float s0 = sc[nl], s1 = sc[nl + 1];
            float2 v0 = make_float2(acc[mi][nj][0] * s0, acc[mi][nj][1] * s1);
            float2 v1 = make_float2(acc[mi][nj][2] * s0, acc[mi][nj][3] * s1);
            *reinterpret_cast<float2*>(o0 + nl) = v0;
            *reinterpret_cast<float2*>(o1 + nl) = v1;
        }
    }
}

// ---------------------------------------------------------------------------
// Launch
// ---------------------------------------------------------------------------
extern "C" void kernel_launch(void* const* d_in, const int* in_sizes, int n_in,
                              void* d_out, int out_size) {
    const float* x   = (const float*)d_in[0];  // [8192, 4096] fp32
    const int*   wq  = (const int*)d_in[1];    // [4096, 4096] int32 (int8 values)
    const float* sc  = (const float*)d_in[2];  // [4096] fp32
    float*       out = (float*)d_out;          // [8192, 4096] fp32

    cvt_a_kernel<<<(int)(((size_t)MT * KT / 8) / 256), 256>>>(x);   // 16384 blocks
    cvt_b_kernel<<<(int)(((size_t)NT * KT / 8) / 256), 256>>>(wq);  //  8192 blocks

    cudaFuncSetAttribute(gemm_kernel,
                         cudaFuncAttributeMaxDynamicSharedMemorySize, SMEM_TOTAL);
    gemm_kernel<<<GRID_M * GRID_N, 256, SMEM_TOTAL>>>(sc, out);
}

// round 17
// speedup vs baseline: 2.2640x; 1.0623x over previous
#include <cuda_runtime.h>
#include <cuda_fp16.h>
#include <cstdint>
#include <cstddef>

// ============================================================================
// WeightOnlyInt8Linear: out[m,n] = (x[m,:] . w[n,:]) * scale[n]
//   M = 8192, N = 4096, K = 4096; x fp32, w int8-valued delivered as INT32,
//   scale fp32, out fp32.
//
// R16: 780.6 us, rel_err 2.08e-4 (fp16 path). GEMM at ~33% of legacy-HMMA
// roofline (~240 us); bottleneck = latency bubbles at 1 CTA/SM (2 warps/SMSP).
// R17: CTA 128x128 (warp tile 64x32), NS=3 -> 96.5KB smem -> 2 CTAs/SM
// (4 warps/SMSP), explicit fragment double-buffering across k16 steps.
// mma.sync.m16n8k16.f16 + ldmatrix + SW128 + cp.async (sm_103 baseline ISA).
// ============================================================================

static constexpr int MT = 8192;
static constexpr int NT = 4096;
static constexpr int KT = 4096;                // fp16 K
static constexpr int ROWB = KT * 2;            // 8192 B per row in g_A/g_B

static constexpr int BM = 128;
static constexpr int BN = 128;
static constexpr int NITER = KT / 64;          // 64 k-stages of 64 fp16 (128B)
static constexpr int NS = 3;                   // pipeline stages

static constexpr int B_OFF       = BM * 128;              // 16384
static constexpr int STAGE_BYTES = (BM + BN) * 128;       // 32768
static constexpr int SC_OFF      = NS * STAGE_BYTES;      // 98304
static constexpr int SMEM_TOTAL  = SC_OFF + BN * 4;       // 98816 (2/SM: 193KB)

static constexpr int GRID_M = MT / BM;         // 64
static constexpr int GRID_N = NT / BN;         // 32
static constexpr int GROUP_M = 8;              // CTA swizzle group width

// Scratch: __device__ globals are the sanctioned alloc-free path.
__device__ __align__(1024) __half g_A[(size_t)MT * KT];   // 64 MB
__device__ __align__(1024) __half g_B[(size_t)NT * KT];   // 32 MB

#define SW128(o) ((o) ^ (((o) >> 3) & 0x70))

__device__ __forceinline__ uint32_t smem_u32(const void* p) {
    uint32_t a;
    asm("{ .reg .u64 t; cvta.to.shared.u64 t, %1; cvt.u32.u64 %0, t; }"
        : "=r"(a) : "l"(p));
    return a;
}

__device__ __forceinline__ void cp_async16(uint32_t smem_addr, const void* gmem) {
    asm volatile("cp.async.cg.shared.global [%0], [%1], 16;"
                 :: "r"(smem_addr), "l"(gmem) : "memory");
}
#define CP_COMMIT() asm volatile("cp.async.commit_group;" ::: "memory")
#define CP_WAIT1()  asm volatile("cp.async.wait_group 1;" ::: "memory")
#define CP_WAIT0()  asm volatile("cp.async.wait_group 0;" ::: "memory")

__device__ __forceinline__ void ldsm4(uint32_t* r, uint32_t addr) {
    asm volatile("ldmatrix.sync.aligned.m8n8.x4.shared.b16 {%0,%1,%2,%3}, [%4];"
                 : "=r"(r[0]), "=r"(r[1]), "=r"(r[2]), "=r"(r[3]) : "r"(addr));
}

__device__ __forceinline__ void mma16816(float* d, const uint32_t* a,
                                         uint32_t b0, uint32_t b1) {
    asm volatile(
        "mma.sync.aligned.m16n8k16.row.col.f32.f16.f16.f32 "
        "{%0,%1,%2,%3}, {%4,%5,%6,%7}, {%8,%9}, {%0,%1,%2,%3};\n"
        : "+f"(d[0]), "+f"(d[1]), "+f"(d[2]), "+f"(d[3])
        : "r"(a[0]), "r"(a[1]), "r"(a[2]), "r"(a[3]), "r"(b0), "r"(b1));
}

// ---------------------------------------------------------------------------
// Phase 1a: fp32 x -> fp16 rows of A' (8 elems / thread)
// ---------------------------------------------------------------------------
__global__ void cvt_a_kernel(const float* __restrict__ x) {
    size_t i = (size_t)blockIdx.x * blockDim.x + threadIdx.x;
    const float4* x4 = reinterpret_cast<const float4*>(x) + i * 2;
    float4 v0 = x4[0];
    float4 v1 = x4[1];
    uint4 u;
    __half* o = reinterpret_cast<__half*>(&u);
    o[0] = __float2half_rn(v0.x); o[1] = __float2half_rn(v0.y);
    o[2] = __float2half_rn(v0.z); o[3] = __float2half_rn(v0.w);
    o[4] = __float2half_rn(v1.x); o[5] = __float2half_rn(v1.y);
    o[6] = __float2half_rn(v1.z); o[7] = __float2half_rn(v1.w);
    reinterpret_cast<uint4*>(g_A)[i] = u;
}

// ---------------------------------------------------------------------------
// Phase 1b: INT32 weights (int8 values, exact in fp16) -> fp16 rows of B'
// ---------------------------------------------------------------------------
__global__ void cvt_b_kernel(const int* __restrict__ w) {
    size_t i = (size_t)blockIdx.x * blockDim.x + threadIdx.x;
    const int4* w4 = reinterpret_cast<const int4*>(w) + i * 2;
    int4 c0 = w4[0];
    int4 c1 = w4[1];
    uint4 u;
    __half* o = reinterpret_cast<__half*>(&u);
    o[0] = __float2half_rn((float)c0.x); o[1] = __float2half_rn((float)c0.y);
    o[2] = __float2half_rn((float)c0.z); o[3] = __float2half_rn((float)c0.w);
    o[4] = __float2half_rn((float)c1.x); o[5] = __float2half_rn((float)c1.y);
    o[6] = __float2half_rn((float)c1.z); o[7] = __float2half_rn((float)c1.w);
    reinterpret_cast<uint4*>(g_B)[i] = u;
}

// ---------------------------------------------------------------------------
// Phase 2: fp16 mma.sync GEMM, 128x128 CTA tile, 3-stage cp.async pipeline,
// 2 CTAs/SM. 256 threads = 8 warps in 2(m) x 4(n); warp tile 64x32.
// Fragment double-buffering: ldmatrix for k-step s+1 issued before MMAs of s.
// ---------------------------------------------------------------------------
__global__ void __launch_bounds__(256, 2)
gemm_kernel(const float* __restrict__ scaler, float* __restrict__ out) {
    extern __shared__ char smem[];
    const uint32_t sb = smem_u32(smem);
    const int tid  = threadIdx.x;
    const int lane = tid & 31;
    const int wid  = tid >> 5;
    const int wm   = wid >> 2;   // 0..1 -> m offset 64*wm
    const int wn   = wid & 3;    // 0..3 -> n offset 32*wn

    // CTA swizzle: waves cover GROUP_M m-tiles x GRID_N n-tiles.
    const int pid        = blockIdx.x;
    const int group_size = GROUP_M * GRID_N;     // 256
    const int group_id   = pid / group_size;
    const int pid_in     = pid - group_id * group_size;
    const int m_tile     = group_id * GROUP_M + (pid_in % GROUP_M);
    const int n_tile     = pid_in / GROUP_M;
    const int m0 = m_tile * BM;
    const int n0 = n_tile * BN;

    if (tid < BN)
        reinterpret_cast<float*>(smem + SC_OFF)[tid] = scaler[n0 + tid];

    // --- cp.async assignment: A 4 chunks, B 4 chunks (16B each) per thread --
    const int lrow = tid >> 3;   // 0..31
    const int lcol = tid & 7;    // 16B column
    uint32_t sA[4], sBs[4];
#pragma unroll
    for (int j = 0; j < 4; j++) {
        uint32_t off = SW128((uint32_t)((lrow + 32 * j) * 128 + lcol * 16));
        sA[j]  = sb + off;
        sBs[j] = sb + (uint32_t)B_OFF + off;
    }
    const char* gAb = reinterpret_cast<const char*>(g_A)
                    + (size_t)(m0 + lrow) * ROWB + lcol * 16;
    const char* gBb = reinterpret_cast<const char*>(g_B)
                    + (size_t)(n0 + lrow) * ROWB + lcol * 16;

    // --- ldmatrix address precompute (row & 7 == lane & 7 for all frags) ----
    const uint32_t swmask = (uint32_t)(lane & 7) << 4;
    const uint32_t lc16   = (uint32_t)(lane >> 4) << 4;  // k-halves split
    uint32_t preA[4], preB[2];
#pragma unroll
    for (int mi = 0; mi < 4; mi++)
        preA[mi] = (uint32_t)((wm * 64 + mi * 16 + (lane & 15)) * 128) + lc16;
#pragma unroll
    for (int bi = 0; bi < 2; bi++)
        preB[bi] = (uint32_t)B_OFF
                 + (uint32_t)((wn * 32 + bi * 16 + (lane & 15)) * 128) + lc16;

    float acc[4][4][4];
#pragma unroll
    for (int mi = 0; mi < 4; mi++)
#pragma unroll
        for (int nj = 0; nj < 4; nj++)
#pragma unroll
            for (int c = 0; c < 4; c++) acc[mi][nj][c] = 0.0f;

    // --- prologue: stages 0..NS-2 ------------------------------------------
#pragma unroll
    for (int p = 0; p < NS - 1; p++) {
        uint32_t st = (uint32_t)(p * STAGE_BYTES);
        int go = p * 128;
#pragma unroll
        for (int j = 0; j < 4; j++) {
            cp_async16(sA[j] + st, gAb + (size_t)j * 32 * ROWB + go);
            cp_async16(sBs[j] + st, gBb + (size_t)j * 32 * ROWB + go);
        }
        CP_COMMIT();
    }

    // --- mainloop -----------------------------------------------------------
    for (int it = 0; it < NITER; it++) {
        CP_WAIT1();            // stage `it` resident (<= NS-2 groups pending)
        __syncthreads();       // all warps done with stage (it-1)%NS

        const int jt = it + NS - 1;
        if (jt < NITER) {      // refill slot (it-1)%NS
            uint32_t st = (uint32_t)((jt % NS) * STAGE_BYTES);
            int go = jt * 128;
#pragma unroll
            for (int j = 0; j < 4; j++) {
                cp_async16(sA[j] + st, gAb + (size_t)j * 32 * ROWB + go);
                cp_async16(sBs[j] + st, gBb + (size_t)j * 32 * ROWB + go);
            }
        }
        CP_COMMIT();           // empty group in tail keeps wait_group math fixed

        const uint32_t stage = sb + (uint32_t)((it % NS) * STAGE_BYTES);

        // Fragment double-buffer across the 4 k16 steps.
        uint32_t af[2][4][4], bfr[2][2][4];
#pragma unroll
        for (int mi = 0; mi < 4; mi++)
            ldsm4(af[0][mi], stage + (preA[mi] ^ swmask));
#pragma unroll
        for (int bi = 0; bi < 2; bi++)
            ldsm4(bfr[0][bi], stage + (preB[bi] ^ swmask));

#pragma unroll
        for (int ks = 0; ks < 4; ks++) {
            const int cur = ks & 1;
            const int nxt = cur ^ 1;
            if (ks < 3) {  // prefetch k-step ks+1 before issuing MMAs of ks
#pragma unroll
                for (int mi = 0; mi < 4; mi++)
                    ldsm4(af[nxt][mi],
                          stage + ((preA[mi] + (ks + 1) * 32) ^ swmask));
#pragma unroll
                for (int bi = 0; bi < 2; bi++)
                    ldsm4(bfr[nxt][bi],
                          stage + ((preB[bi] + (ks + 1) * 32) ^ swmask));
            }
#pragma unroll
            for (int mi = 0; mi < 4; mi++) {
#pragma unroll
                for (int nj = 0; nj < 4; nj++) {
                    uint32_t b0 = bfr[cur][nj >> 1][nj & 1];
                    uint32_t b1 = bfr[cur][nj >> 1][(nj & 1) + 2];
                    mma16816(acc[mi][nj], af[cur][mi], b0, b1);
                }
            }
        }
    }
    CP_WAIT0();  // drain before exit

    // --- epilogue: scale and store (d0,d1 row r; d2,d3 row r+8) -------------
    const float* sc = reinterpret_cast<const float*>(smem + SC_OFF);
#pragma unroll
    for (int mi = 0; mi < 4; mi++) {
        int r = m0 + wm * 64 + mi * 16 + (lane >> 2);
        float* o0 = out + (size_t)r * NT + n0;
        float* o1 = out + (size_t)(r + 8) * NT + n0;
#pragma unroll
        for (int nj = 0; nj < 4; nj++) {
            int nl = wn * 32 + nj * 8 + (lane & 3) * 2;
            float s0 = sc[nl], s1 = sc[nl + 1];
            float2 v0 = make_float2(acc[mi][nj][0] * s0, acc[mi][nj][1] * s1);
            float2 v1 = make_float2(acc[mi][nj][2] * s0, acc[mi][nj][3] * s1);
            *reinterpret_cast<float2*>(o0 + nl) = v0;
            *reinterpret_cast<float2*>(o1 + nl) = v1;
        }
    }
}

// ---------------------------------------------------------------------------
// Launch
// ---------------------------------------------------------------------------
extern "C" void kernel_launch(void* const* d_in, const int* in_sizes, int n_in,
                              void* d_out, int out_size) {
    const float* x   = (const float*)d_in[0];  // [8192, 4096] fp32
    const int*   wq  = (const int*)d_in[1];    // [4096, 4096] int32 (int8 values)
    const float* sc  = (const float*)d_in[2];  // [4096] fp32
    float*       out = (float*)d_out;          // [8192, 4096] fp32

    cvt_a_kernel<<<(int)(((size_t)MT * KT / 8) / 256), 256>>>(x);   // 16384 blocks
    cvt_b_kernel<<<(int)(((size_t)NT * KT / 8) / 256), 256>>>(wq);  //  8192 blocks

    cudaFuncSetAttribute(gemm_kernel,
                         cudaFuncAttributeMaxDynamicSharedMemorySize, SMEM_TOTAL);
    gemm_kernel<<<GRID_M * GRID_N, 256, SMEM_TOTAL>>>(sc, out);
}